// round 4
// baseline (speedup 1.0000x reference)
#include <cuda_runtime.h>
#include <cstdint>

// Problem constants (fixed by the reference)
#define NSLOT 1048576u      // N
#define WDIM  64            // W
#define EPSF  1e-8f

#define HIST_BUCKETS 2048   // u in [0,1) -> bucket = float_bits(u)>>19 in [0, 2032]
#define HIST_SHIFT   19
#define SORT_CAP     8192   // max gathered candidates
#define KSEL         256    // minimum number of smallest elements to gather

#define MAIN_TPB     512
#define MAIN_BLOCKS  (NSLOT / MAIN_TPB)    // 2048 blocks, thread-per-row (warp = 32 rows)

// ---------------- scratch (device globals; no allocations allowed) ------------
__device__ float              g_partial_sum[MAIN_BLOCKS];
__device__ unsigned           g_hist[HIST_BUCKETS];
__device__ float              g_inv_sum;
__device__ unsigned           g_thresh;   // gathered iff float_bits(usage) < g_thresh
__device__ unsigned           g_count;
__device__ unsigned long long g_pairs[SORT_CAP];
__device__ float              g_scale;    // beta / max(||key||, eps)
__device__ float              g_beta;     // softmax shift (sim*beta <= beta)

// ---------------- helpers ------------------------------------------------------
__device__ __forceinline__ float warp_sum(float v) {
    #pragma unroll
    for (int o = 16; o; o >>= 1) v += __shfl_xor_sync(0xffffffffu, v, o);
    return v;
}

// ---------------- kernels ------------------------------------------------------

// 1 block, 256 threads: zero hist/count, compute key norm scale + shift.
__global__ void k_prep(const float* __restrict__ key, const float* __restrict__ beta) {
    const int t = threadIdx.x;
    #pragma unroll
    for (int i = 0; i < HIST_BUCKETS / 256; i++) g_hist[t + i * 256] = 0u;
    if (t == 0) g_count = 0u;
    if (t < 32) {
        float a = key[t], b = key[t + 32];
        float s = warp_sum(a * a + b * b);
        if (t == 0) {
            float kn = fmaxf(sqrtf(s), EPSF);
            float bv = beta[0];
            g_scale = bv / kn;
            g_beta  = bv;
        }
    }
}

// Fused main pass. Warp owns 32 consecutive rows; each iteration the warp loads
// 512 contiguous bytes (2 rows) fully coalesced and reduces per-row dot/norm
// with xor-butterfly shuffles over 16-lane halves. No data staging in smem.
//   out[0..N)   = exp(sim*beta - beta)   (unnormalized content weighting)
//   out[N..2N)  = retention
//   out[2N..3N) = usage
//   out[3N..4N) = 0                       (allocation init)
// plus usage histogram (warp-aggregated atomics) and per-block sums of e.
__global__ void __launch_bounds__(MAIN_TPB) k_main(
    const float* __restrict__ mem, const float* __restrict__ key,
    const float* __restrict__ fg,  const float* __restrict__ rw,
    const float* __restrict__ pu,  const float* __restrict__ ww,
    float* __restrict__ out)
{
    __shared__ float ssum[MAIN_TPB / 32];

    const int t    = threadIdx.x;
    const int lane = t & 31;
    const int warp = t >> 5;

    // this lane always multiplies against the same key chunk
    const float4 kc = reinterpret_cast<const float4*>(key)[lane & 15];

    const unsigned rowbase = blockIdx.x * (unsigned)MAIN_TPB + (unsigned)(warp * 32);
    const float4* g = reinterpret_cast<const float4*>(mem) + (size_t)rowbase * 16;

    float my_dot = 0.0f, my_nrm = 0.0f;
    #pragma unroll
    for (int j = 0; j < 16; j++) {
        float4 v = g[j * 32 + lane];                   // warp: 512B contiguous (rows 2j, 2j+1)
        float d = v.x * kc.x + v.y * kc.y + v.z * kc.z + v.w * kc.w;
        float n = v.x * v.x + v.y * v.y + v.z * v.z + v.w * v.w;
        #pragma unroll
        for (int o = 8; o; o >>= 1) {                  // butterfly within 16-lane halves
            d += __shfl_xor_sync(0xffffffffu, d, o);
            n += __shfl_xor_sync(0xffffffffu, n, o);
        }
        float d2 = __shfl_xor_sync(0xffffffffu, d, 16);   // other half's row sum
        float n2 = __shfl_xor_sync(0xffffffffu, n, 16);
        // row 2j (lower half) / row 2j+1 (upper half) values, visible to all lanes
        float dlow  = (lane < 16) ? d  : d2;
        float dhigh = (lane < 16) ? d2 : d;
        float nlow  = (lane < 16) ? n  : n2;
        float nhigh = (lane < 16) ? n2 : n;
        if ((lane >> 1) == j) {                        // thread `lane` owns row rowbase+lane
            my_dot = (lane & 1) ? dhigh : dlow;
            my_nrm = (lane & 1) ? nhigh : nlow;
        }
    }

    const unsigned i = blockIdx.x * (unsigned)MAIN_TPB + (unsigned)t;   // = rowbase + lane

    float rn = fmaxf(sqrtf(my_nrm), EPSF);
    float e  = expf(my_dot * g_scale / rn - g_beta);   // exp(sim*beta - beta) in (0,1]
    out[i] = e;

    // retention / usage (coalesced, thread-per-row)
    float4 fg4 = *reinterpret_cast<const float4*>(fg);
    float4 r4  = reinterpret_cast<const float4*>(rw)[i];
    float ret = (1.0f - r4.x * fg4.x) * (1.0f - r4.y * fg4.y)
              * (1.0f - r4.z * fg4.z) * (1.0f - r4.w * fg4.w);
    out[NSLOT + i] = ret;

    float p = pu[i], w = ww[i];
    float u = (p + w - p * w) * ret;
    out[2u * NSLOT + i] = u;
    out[3u * NSLOT + i] = 0.0f;

    // histogram with warp aggregation (merge lanes hitting the same bucket)
    unsigned b = __float_as_uint(u) >> HIST_SHIFT;
    if (b >= HIST_BUCKETS) b = HIST_BUCKETS - 1;
    unsigned peers = __match_any_sync(0xffffffffu, b);
    int leader = __ffs(peers) - 1;
    if (lane == leader) atomicAdd(&g_hist[b], (unsigned)__popc(peers));

    // block partial sum of e
    float sum = warp_sum(e);
    if (lane == 0) ssum[warp] = sum;
    __syncthreads();
    if (t == 0) {
        float tot = ssum[0];
        #pragma unroll
        for (int j = 1; j < MAIN_TPB / 32; j++) tot += ssum[j];
        g_partial_sum[blockIdx.x] = tot;
    }
}

// 1 block, 1024 threads: reduce partial sums -> 1/sum; pick gather threshold
// from histogram (first bucket covering >= KSEL smallest, capped at SORT_CAP).
__global__ void k_mid() {
    const int t = threadIdx.x;
    __shared__ float sm[32];

    // ---- sum reduce
    float s = 0.0f;
    #pragma unroll
    for (int j = 0; j < MAIN_BLOCKS / 1024; j++) s += g_partial_sum[t + j * 1024];
    s = warp_sum(s);
    int lane = t & 31, warp = t >> 5;
    if (lane == 0) sm[warp] = s;
    __syncthreads();
    if (t < 32) {
        float v = sm[t];
        v = warp_sum(v);
        if (t == 0) g_inv_sum = 1.0f / v;
    }

    // ---- histogram threshold selection (2048 buckets, 2 per thread)
    __shared__ unsigned tsum[1024];
    __shared__ int sT1, sT2;
    unsigned l0 = g_hist[t * 2], l1 = g_hist[t * 2 + 1];
    tsum[t] = l0 + l1;
    if (t == 0) { sT1 = HIST_BUCKETS - 1; sT2 = 0x7fffffff; }
    __syncthreads();
    for (int off = 1; off < 1024; off <<= 1) {
        unsigned v = (t >= off) ? tsum[t - off] : 0u;
        __syncthreads();
        tsum[t] += v;
        __syncthreads();
    }
    unsigned cum = (t == 0) ? 0u : tsum[t - 1];
    cum += l0;
    if (cum >= KSEL)    atomicMin(&sT1, t * 2);
    if (cum > SORT_CAP) atomicMin(&sT2, t * 2);
    cum += l1;
    if (cum >= KSEL)    atomicMin(&sT1, t * 2 + 1);
    if (cum > SORT_CAP) atomicMin(&sT2, t * 2 + 1);
    __syncthreads();
    if (t == 0) {
        int T = sT1;
        if (sT2 != 0x7fffffff && sT2 - 1 < T) T = sT2 - 1;
        if (T < 0) T = 0;
        g_thresh = ((unsigned)(T + 1)) << HIST_SHIFT;
    }
}

// Normalize content weighting + gather smallest usages. 4 float4 per thread,
// loads front-batched for MLP.
#define P2_BLOCKS 256
#define P2_STRIDE (P2_BLOCKS * 256)      // 65536 float4 per sweep
__global__ void __launch_bounds__(256) k_pass2(float* __restrict__ out) {
    const unsigned base = blockIdx.x * 256u + threadIdx.x;   // float4 index
    float4* o4 = reinterpret_cast<float4*>(out);
    const float inv = g_inv_sum;
    const unsigned th = g_thresh;

    float4 e[4], u[4];
    #pragma unroll
    for (int k = 0; k < 4; k++) {
        unsigned q = base + k * P2_STRIDE;
        e[k] = o4[q];
        u[k] = o4[(2u * NSLOT) / 4 + q];
    }
    #pragma unroll
    for (int k = 0; k < 4; k++) {
        unsigned q = base + k * P2_STRIDE;
        e[k].x *= inv; e[k].y *= inv; e[k].z *= inv; e[k].w *= inv;
        o4[q] = e[k];
        unsigned idx0 = q * 4u;
        #pragma unroll
        for (int c = 0; c < 4; c++) {
            float uv = (c == 0) ? u[k].x : (c == 1) ? u[k].y : (c == 2) ? u[k].z : u[k].w;
            if (__float_as_uint(uv) < th) {
                unsigned pos = atomicAdd(&g_count, 1u);
                if (pos < SORT_CAP)
                    g_pairs[pos] = ((unsigned long long)__float_as_uint(uv) << 32)
                                 | (unsigned long long)(idx0 + c);
            }
        }
    }
}

// Single block: bitonic sort (dynamic power-of-two size) of (usage_bits:index)
// pairs -- 64-bit key gives the stable order of jnp argsort -- then serial
// cumprod with early exit once the product underflows to exactly 0.
__global__ void k_sortalloc(float* __restrict__ out) {
    extern __shared__ unsigned long long sp[];
    const unsigned count = min(g_count, (unsigned)SORT_CAP);
    unsigned n = 2;
    while (n < count) n <<= 1;

    const int t = threadIdx.x;
    for (unsigned i = t; i < n; i += 1024)
        sp[i] = (i < count) ? g_pairs[i] : 0xFFFFFFFFFFFFFFFFull;
    __syncthreads();

    for (unsigned k = 2; k <= n; k <<= 1) {
        for (unsigned j = k >> 1; j > 0; j >>= 1) {
            for (unsigned i = t; i < n; i += 1024) {
                unsigned ixj = i ^ j;
                if (ixj > i) {
                    bool up = ((i & k) == 0);
                    unsigned long long a = sp[i], b = sp[ixj];
                    if ((a > b) == up) { sp[i] = b; sp[ixj] = a; }
                }
            }
            __syncthreads();
        }
    }

    if (t == 0) {
        float prod = 1.0f, prev = 0.0f;
        for (unsigned j = 0; j < count; j++) {
            unsigned long long p = sp[j];
            float    sv  = __uint_as_float((unsigned)(p >> 32));
            unsigned idx = (unsigned)(p & 0xFFFFFFFFull);
            float a = (j == 0) ? (1.0f - sv) : (1.0f - prev) * prod;
            out[3u * NSLOT + idx] = a;
            prod *= sv;
            prev  = sv;
            if (prod == 0.0f) break;   // remaining allocations are exactly 0
        }
    }
}

// ---------------- launch --------------------------------------------------------
extern "C" void kernel_launch(void* const* d_in, const int* in_sizes, int n_in,
                              void* d_out, int out_size)
{
    const float* key  = (const float*)d_in[0];  // desired_content (64)
    const float* mem  = (const float*)d_in[1];  // memory (N*W)
    const float* beta = (const float*)d_in[2];  // key_strength (1)
    const float* fg   = (const float*)d_in[3];  // free_gate (4)
    const float* rw   = (const float*)d_in[4];  // read_weighting (N*4)
    const float* pu   = (const float*)d_in[5];  // previous_usage (N)
    const float* ww   = (const float*)d_in[6];  // write_weighting (N)
    float* out = (float*)d_out;                 // (4, N) float32

    cudaFuncSetAttribute(k_sortalloc, cudaFuncAttributeMaxDynamicSharedMemorySize,
                         SORT_CAP * (int)sizeof(unsigned long long));

    k_prep      <<<1, 256>>>(key, beta);
    k_main      <<<MAIN_BLOCKS, MAIN_TPB>>>(mem, key, fg, rw, pu, ww, out);
    k_mid       <<<1, 1024>>>();
    k_pass2     <<<P2_BLOCKS, 256>>>(out);
    k_sortalloc <<<1, 1024, SORT_CAP * (int)sizeof(unsigned long long)>>>(out);
}